// round 4
// baseline (speedup 1.0000x reference)
#include <cuda_runtime.h>

// CapsuleLayer dynamic routing, algebraically collapsed:
//   b[n,m] = x[n,:] @ Pacc[:,m]   (Pacc accumulates log2e * W@v across iterations)
//   s[m,:] = (1/Z) (e^T x) W[:,m,:],  v = squash(s),  Pacc[:,m] += log2e*W[:,m,:] v
// u_hat (268MB) never materialized. Softmax stabilized by Cauchy-Schwarz bound
// |l| <= max_n||x_n|| * ||Pacc_col||, in log2 domain so exp = single EX2.
// R4: back to C=2 / 512 threads (4 warps/SMSP for latency hiding), keeping
//     log2-EX2, folded bound, double-buffered prefetch; 3-level reduction.

#define NROW    2048
#define DIN     16
#define XSTRIDE 20
#define THREADS 512
#define LOG2E   1.4426950408889634f

struct Smem {
  float xs[NROW * XSTRIDE];     // padded x rows (conflict-free stride 80B)
  float Wdc[16 * 16 * 16];      // [ml][d][c]
  float Wcd[16 * 16 * 16];      // [ml][c][d]
  float Pacc[16 * 16];          // [ml][d]  (scaled by log2e)
  float party[2][4][16][16];    // [chunk][lanegrp][ml][d]
  float partZ[2][4][16];        // [chunk][lanegrp][ml]
  float wpart[16][16];          // per-warp partial column sums of x
  float wmax[16];               // per-warp max row-norm^2
  float sumx[16];               // sum over n of x[n,d]
  float vbuf[16 * 16];          // [ml][c]
  float bnd[16];                // softmax shift bound per ml (log2 domain)
  float mxnorm;
  float pad[3];
};

typedef unsigned long long ull;

__device__ __forceinline__ ull mul2(ull a, ull b) {
  ull d; asm("mul.rn.f32x2 %0, %1, %2;" : "=l"(d) : "l"(a), "l"(b)); return d;
}
__device__ __forceinline__ ull add2(ull a, ull b) {
  ull d; asm("add.rn.f32x2 %0, %1, %2;" : "=l"(d) : "l"(a), "l"(b)); return d;
}
__device__ __forceinline__ ull fma2(ull a, ull b, ull c) {
  ull d; asm("fma.rn.f32x2 %0, %1, %2, %3;" : "=l"(d) : "l"(a), "l"(b), "l"(c)); return d;
}
__device__ __forceinline__ ull pack2(float x) {
  ull d; asm("mov.b64 %0, {%1, %1};" : "=l"(d) : "f"(x)); return d;
}
__device__ __forceinline__ ull packlh(float lo, float hi) {
  ull d; asm("mov.b64 %0, {%1, %2};" : "=l"(d) : "f"(lo), "f"(hi)); return d;
}
__device__ __forceinline__ float hadd2(ull a) {
  float lo, hi; asm("mov.b64 {%0, %1}, %2;" : "=f"(lo), "=f"(hi) : "l"(a)); return lo + hi;
}
__device__ __forceinline__ float ex2f(float x) {
  float r; asm("ex2.approx.f32 %0, %1;" : "=f"(r) : "f"(x)); return r;
}

__device__ __forceinline__ void loadx(ull (&dst)[8], const float* base) {
  const ulonglong2* xp = reinterpret_cast<const ulonglong2*>(base);
  ulonglong2 q0 = xp[0], q1 = xp[1], q2 = xp[2], q3 = xp[3];
  dst[0] = q0.x; dst[1] = q0.y; dst[2] = q1.x; dst[3] = q1.y;
  dst[4] = q2.x; dst[5] = q2.y; dst[6] = q3.x; dst[7] = q3.y;
}

__device__ __forceinline__ void docaps(const ull (&xx)[8], const ull (&p)[2][8],
                                       const ull (&ib)[2], ull (&y)[2][8],
                                       float (&Z)[2]) {
#pragma unroll
  for (int c = 0; c < 2; ++c) {
    ull a0 = fma2(xx[0], p[c][0], ib[c]);   // ib = {-bnd, 0}: bound pre-folded
    ull a1 = mul2(xx[1], p[c][1]);
#pragma unroll
    for (int j = 1; j < 4; ++j) {
      a0 = fma2(xx[2 * j],     p[c][2 * j],     a0);
      a1 = fma2(xx[2 * j + 1], p[c][2 * j + 1], a1);
    }
    float l = hadd2(add2(a0, a1));
    float e = ex2f(l);
    Z[c] += e;
    ull e2 = pack2(e);
#pragma unroll
    for (int j = 0; j < 8; ++j) y[c][j] = fma2(e2, xx[j], y[c][j]);
  }
}

__global__ void __launch_bounds__(THREADS, 1)
caps_routing_kernel(const float* __restrict__ X, const float* __restrict__ Wg,
                    float* __restrict__ Y) {
  extern __shared__ char smraw[];
  Smem* sm = reinterpret_cast<Smem*>(smraw);
  const int tid  = threadIdx.x;
  const int lane = tid & 31;
  const int w    = tid >> 5;
  const int b    = blockIdx.x >> 1;
  const int m0   = (blockIdx.x & 1) * 16;

  if (tid < 256) sm->Pacc[tid] = 0.f;
  if (tid < 16)  sm->bnd[tid]  = 0.f;

  // ---- Load x tile (128KB) into padded smem; fold in column sums + max row norm ----
  const float4* Xb = reinterpret_cast<const float4*>(X + (size_t)b * NROW * DIN);
  const int q = tid & 3;
  float4 s4 = make_float4(0.f, 0.f, 0.f, 0.f);
  float mloc = 0.f;
#pragma unroll
  for (int i = 0; i < 16; ++i) {
    int idx = tid + THREADS * i;
    int n = idx >> 2;
    float4 v = Xb[idx];
    *reinterpret_cast<float4*>(&sm->xs[n * XSTRIDE + q * 4]) = v;
    s4.x += v.x; s4.y += v.y; s4.z += v.z; s4.w += v.w;
    float qd = v.x * v.x + v.y * v.y + v.z * v.z + v.w * v.w;
    qd += __shfl_xor_sync(0xffffffffu, qd, 1);
    qd += __shfl_xor_sync(0xffffffffu, qd, 2);
    mloc = fmaxf(mloc, qd);
  }
#pragma unroll
  for (int off = 4; off < 32; off <<= 1) {
    s4.x += __shfl_xor_sync(0xffffffffu, s4.x, off);
    s4.y += __shfl_xor_sync(0xffffffffu, s4.y, off);
    s4.z += __shfl_xor_sync(0xffffffffu, s4.z, off);
    s4.w += __shfl_xor_sync(0xffffffffu, s4.w, off);
    mloc = fmaxf(mloc, __shfl_xor_sync(0xffffffffu, mloc, off));
  }
  if (lane < 4) *reinterpret_cast<float4*>(&sm->wpart[w][lane * 4]) = s4;
  if (lane == 0) sm->wmax[w] = mloc;

  // ---- Load W slices in two layouts ----
#pragma unroll
  for (int i = 0; i < 8; ++i) {
    int idx2 = tid + THREADS * i;         // [ml][d][c]
    int ml = idx2 >> 8, d = (idx2 >> 4) & 15, c = idx2 & 15;
    float val = Wg[d * 512 + (m0 + ml) * 16 + c];
    sm->Wdc[idx2] = val;
    sm->Wcd[ml * 256 + c * 16 + d] = val;
  }
  __syncthreads();

  if (tid < 16) {
    float s = 0.f;
#pragma unroll
    for (int ww = 0; ww < 16; ++ww) s += sm->wpart[ww][tid];
    sm->sumx[tid] = s;
  }
  if (tid == 16) {
    float mx = 0.f;
#pragma unroll
    for (int ww = 0; ww < 16; ++ww) mx = fmaxf(mx, sm->wmax[ww]);
    sm->mxnorm = sqrtf(mx);
  }

  const int g     = w & 7;      // capsule pair group
  const int chunk = w >> 3;     // row chunk (0: 0-1023, 1: 1024-2047)
  const int mlb   = 2 * g;
  const float* xbase = &sm->xs[(chunk * 1024 + lane) * XSTRIDE];
  const int XSTEP = 32 * XSTRIDE;

  for (int it = 0; it < 3; ++it) {
    if (it > 0) {
      // ---- fused logit(log2) + EX2 + weighted-sum pass, double-buffered x ----
      ull p[2][8], y[2][8], ib[2];
      float Z[2];
#pragma unroll
      for (int c = 0; c < 2; ++c) {
#pragma unroll
        for (int j = 0; j < 8; ++j) {
          p[c][j] = *reinterpret_cast<const ull*>(&sm->Pacc[(mlb + c) * 16 + 2 * j]);
          y[c][j] = 0ull;
        }
        ib[c] = packlh(-sm->bnd[mlb + c], 0.f);
        Z[c] = 0.f;
      }
      ull xx[8], xn[8];
      loadx(xx, xbase);
#pragma unroll 1
      for (int s2 = 0; s2 < 15; ++s2) {
        loadx(xn, xbase + (2 * s2 + 1) * XSTEP);
        docaps(xx, p, ib, y, Z);
        loadx(xx, xbase + (2 * s2 + 2) * XSTEP);
        docaps(xn, p, ib, y, Z);
      }
      loadx(xn, xbase + 31 * XSTEP);
      docaps(xx, p, ib, y, Z);
      docaps(xn, p, ib, y, Z);

      // 3-level warp reduction -> 4 partials (lanes 0..3)
#pragma unroll
      for (int off = 16; off >= 4; off >>= 1) {
#pragma unroll
        for (int c = 0; c < 2; ++c) {
          Z[c] += __shfl_xor_sync(0xffffffffu, Z[c], off);
#pragma unroll
          for (int j = 0; j < 8; ++j)
            y[c][j] = add2(y[c][j], __shfl_xor_sync(0xffffffffu, y[c][j], off));
        }
      }
      if (lane < 4) {
#pragma unroll
        for (int c = 0; c < 2; ++c) {
          sm->partZ[chunk][lane][mlb + c] = Z[c];
#pragma unroll
          for (int j = 0; j < 8; ++j)
            *reinterpret_cast<ull*>(&sm->party[chunk][lane][mlb + c][2 * j]) = y[c][j];
        }
      }
    }
    __syncthreads();

    // ---- per-capsule epilogue: s = yW/Z, squash, Pacc += log2e * W v, new bound ----
    if (w < 8) {
      const int ml  = w * 2 + (lane >> 4);
      const int idx = lane & 15;
      float Z, yv;
      if (it == 0) {
        Z = 2048.f;
        yv = 0.f;  // unused
      } else {
        Z = 0.f;
#pragma unroll
        for (int cg = 0; cg < 4; ++cg) Z += sm->partZ[0][cg][ml] + sm->partZ[1][cg][ml];
      }
      float s = 0.f;
#pragma unroll
      for (int d = 0; d < 16; ++d) {
        if (it == 0) {
          yv = sm->sumx[d];
        } else {
          yv = 0.f;
#pragma unroll
          for (int cg = 0; cg < 4; ++cg)
            yv += sm->party[0][cg][ml][d] + sm->party[1][cg][ml][d];
        }
        s += yv * sm->Wdc[(ml * 16 + d) * 16 + idx];
      }
      s *= (1.f / Z);
      float nsq = s * s;
#pragma unroll
      for (int off = 1; off < 16; off <<= 1) nsq += __shfl_xor_sync(0xffffffffu, nsq, off);
      float norm = sqrtf(nsq);
      float fac  = nsq / ((1.f + nsq) * (norm + 1e-7f));
      float v    = s * fac;
      if (it == 2) {
        Y[(size_t)b * 512 + (m0 + ml) * 16 + idx] = v;
      } else {
        sm->vbuf[ml * 16 + idx] = v;
        __syncwarp();
        float pd = 0.f;
#pragma unroll
        for (int c = 0; c < 16; ++c)
          pd += sm->Wcd[(ml * 16 + c) * 16 + idx] * sm->vbuf[ml * 16 + c];
        float pn = sm->Pacc[ml * 16 + idx] + LOG2E * pd;
        sm->Pacc[ml * 16 + idx] = pn;
        float cn = pn * pn;
#pragma unroll
        for (int off = 1; off < 16; off <<= 1) cn += __shfl_xor_sync(0xffffffffu, cn, off);
        if (idx == 0) sm->bnd[ml] = sqrtf(cn) * sm->mxnorm;
      }
    }
    __syncthreads();
  }
}

extern "C" void kernel_launch(void* const* d_in, const int* in_sizes, int n_in,
                              void* d_out, int out_size) {
  (void)in_sizes; (void)n_in; (void)out_size;
  const float* X  = (const float*)d_in[0];   // inputs (64, 2048, 16)
  const float* Wg = (const float*)d_in[1];   // W (16, 32, 16)
  float* Y = (float*)d_out;                  // v (64, 32, 16)
  cudaFuncSetAttribute(caps_routing_kernel,
                       cudaFuncAttributeMaxDynamicSharedMemorySize, (int)sizeof(Smem));
  caps_routing_kernel<<<128, THREADS, sizeof(Smem)>>>(X, Wg, Y);
}

// round 5
// speedup vs baseline: 1.0094x; 1.0094x over previous
#include <cuda_runtime.h>

// CapsuleLayer dynamic routing, algebraically collapsed:
//   b[n,m] = x[n,:] @ Pacc[:,m]   (Pacc accumulates log2e * W@v across iterations)
//   s[m,:] = (1/Z) (e^T x) W[:,m,:],  v = squash(s),  Pacc[:,m] += log2e*W[:,m,:] v
// u_hat (268MB) never materialized. Softmax stabilized by Cauchy-Schwarz bound
// |l| <= max_n||x_n|| * ||Pacc_col||, in log2 domain so exp = single EX2.
// R5: 2 rows per lane per step (4 independent logit/EX2 chains per step) for
//     intra-warp ILP at 16 warps/SM (RF-capped occupancy). C=2, 512 threads.

#define NROW    2048
#define DIN     16
#define XSTRIDE 20
#define THREADS 512
#define LOG2E   1.4426950408889634f

struct Smem {
  float xs[NROW * XSTRIDE];     // padded x rows (conflict-free stride 80B)
  float Wdc[16 * 16 * 16];      // [ml][d][c]
  float Wcd[16 * 16 * 16];      // [ml][c][d]
  float Pacc[16 * 16];          // [ml][d]  (scaled by log2e)
  float party[2][4][16][16];    // [chunk][lanegrp][ml][d]
  float partZ[2][4][16];        // [chunk][lanegrp][ml]
  float wpart[16][16];          // per-warp partial column sums of x
  float wmax[16];               // per-warp max row-norm^2
  float sumx[16];               // sum over n of x[n,d]
  float vbuf[16 * 16];          // [ml][c]
  float bnd[16];                // softmax shift bound per ml (log2 domain)
  float mxnorm;
  float pad[3];
};

typedef unsigned long long ull;

__device__ __forceinline__ ull mul2(ull a, ull b) {
  ull d; asm("mul.rn.f32x2 %0, %1, %2;" : "=l"(d) : "l"(a), "l"(b)); return d;
}
__device__ __forceinline__ ull add2(ull a, ull b) {
  ull d; asm("add.rn.f32x2 %0, %1, %2;" : "=l"(d) : "l"(a), "l"(b)); return d;
}
__device__ __forceinline__ ull fma2(ull a, ull b, ull c) {
  ull d; asm("fma.rn.f32x2 %0, %1, %2, %3;" : "=l"(d) : "l"(a), "l"(b), "l"(c)); return d;
}
__device__ __forceinline__ ull pack2(float x) {
  ull d; asm("mov.b64 %0, {%1, %1};" : "=l"(d) : "f"(x)); return d;
}
__device__ __forceinline__ ull packlh(float lo, float hi) {
  ull d; asm("mov.b64 %0, {%1, %2};" : "=l"(d) : "f"(lo), "f"(hi)); return d;
}
__device__ __forceinline__ float hadd2(ull a) {
  float lo, hi; asm("mov.b64 {%0, %1}, %2;" : "=f"(lo), "=f"(hi) : "l"(a)); return lo + hi;
}
__device__ __forceinline__ float ex2f(float x) {
  float r; asm("ex2.approx.f32 %0, %1;" : "=f"(r) : "f"(x)); return r;
}

__device__ __forceinline__ void loadx(ull (&dst)[8], const float* base) {
  const ulonglong2* xp = reinterpret_cast<const ulonglong2*>(base);
  ulonglong2 q0 = xp[0], q1 = xp[1], q2 = xp[2], q3 = xp[3];
  dst[0] = q0.x; dst[1] = q0.y; dst[2] = q1.x; dst[3] = q1.y;
  dst[4] = q2.x; dst[5] = q2.y; dst[6] = q3.x; dst[7] = q3.y;
}

__global__ void __launch_bounds__(THREADS, 1)
caps_routing_kernel(const float* __restrict__ X, const float* __restrict__ Wg,
                    float* __restrict__ Y) {
  extern __shared__ char smraw[];
  Smem* sm = reinterpret_cast<Smem*>(smraw);
  const int tid  = threadIdx.x;
  const int lane = tid & 31;
  const int w    = tid >> 5;
  const int b    = blockIdx.x >> 1;
  const int m0   = (blockIdx.x & 1) * 16;

  if (tid < 256) sm->Pacc[tid] = 0.f;
  if (tid < 16)  sm->bnd[tid]  = 0.f;

  // ---- Load x tile (128KB) into padded smem; fold in column sums + max row norm ----
  const float4* Xb = reinterpret_cast<const float4*>(X + (size_t)b * NROW * DIN);
  const int q = tid & 3;
  float4 s4 = make_float4(0.f, 0.f, 0.f, 0.f);
  float mloc = 0.f;
#pragma unroll
  for (int i = 0; i < 16; ++i) {
    int idx = tid + THREADS * i;
    int n = idx >> 2;
    float4 v = Xb[idx];
    *reinterpret_cast<float4*>(&sm->xs[n * XSTRIDE + q * 4]) = v;
    s4.x += v.x; s4.y += v.y; s4.z += v.z; s4.w += v.w;
    float qd = v.x * v.x + v.y * v.y + v.z * v.z + v.w * v.w;
    qd += __shfl_xor_sync(0xffffffffu, qd, 1);
    qd += __shfl_xor_sync(0xffffffffu, qd, 2);
    mloc = fmaxf(mloc, qd);
  }
#pragma unroll
  for (int off = 4; off < 32; off <<= 1) {
    s4.x += __shfl_xor_sync(0xffffffffu, s4.x, off);
    s4.y += __shfl_xor_sync(0xffffffffu, s4.y, off);
    s4.z += __shfl_xor_sync(0xffffffffu, s4.z, off);
    s4.w += __shfl_xor_sync(0xffffffffu, s4.w, off);
    mloc = fmaxf(mloc, __shfl_xor_sync(0xffffffffu, mloc, off));
  }
  if (lane < 4) *reinterpret_cast<float4*>(&sm->wpart[w][lane * 4]) = s4;
  if (lane == 0) sm->wmax[w] = mloc;

  // ---- Load W slices in two layouts ----
#pragma unroll
  for (int i = 0; i < 8; ++i) {
    int idx2 = tid + THREADS * i;         // [ml][d][c]
    int ml = idx2 >> 8, d = (idx2 >> 4) & 15, c = idx2 & 15;
    float val = Wg[d * 512 + (m0 + ml) * 16 + c];
    sm->Wdc[idx2] = val;
    sm->Wcd[ml * 256 + c * 16 + d] = val;
  }
  __syncthreads();

  if (tid < 16) {
    float s = 0.f;
#pragma unroll
    for (int ww = 0; ww < 16; ++ww) s += sm->wpart[ww][tid];
    sm->sumx[tid] = s;
  }
  if (tid == 16) {
    float mx = 0.f;
#pragma unroll
    for (int ww = 0; ww < 16; ++ww) mx = fmaxf(mx, sm->wmax[ww]);
    sm->mxnorm = sqrtf(mx);
  }

  const int g     = w & 7;      // capsule pair group
  const int chunk = w >> 3;     // row chunk (0: 0-1023, 1: 1024-2047)
  const int mlb   = 2 * g;
  const float* xbase = &sm->xs[(chunk * 1024 + lane) * XSTRIDE];

  for (int it = 0; it < 3; ++it) {
    if (it > 0) {
      // ---- fused logit(log2) + EX2 + weighted-sum pass, 2 rows/lane/step ----
      ull p[2][8], y[2][8], ib[2];
      float Z0[2], Z1[2];
#pragma unroll
      for (int c = 0; c < 2; ++c) {
#pragma unroll
        for (int j = 0; j < 8; ++j) {
          p[c][j] = *reinterpret_cast<const ull*>(&sm->Pacc[(mlb + c) * 16 + 2 * j]);
          y[c][j] = 0ull;
        }
        ib[c] = packlh(-sm->bnd[mlb + c], 0.f);
        Z0[c] = 0.f; Z1[c] = 0.f;
      }
#pragma unroll 1
      for (int step = 0; step < 16; ++step) {
        ull x0[8], x1[8];
        loadx(x0, xbase + (step * 64) * XSTRIDE);
        loadx(x1, xbase + (step * 64 + 32) * XSTRIDE);
#pragma unroll
        for (int c = 0; c < 2; ++c) {
          ull a0 = fma2(x0[0], p[c][0], ib[c]);   // bound pre-folded
          ull a1 = mul2(x0[1], p[c][1]);
          ull b0 = fma2(x1[0], p[c][0], ib[c]);
          ull b1 = mul2(x1[1], p[c][1]);
#pragma unroll
          for (int j = 1; j < 4; ++j) {
            a0 = fma2(x0[2 * j],     p[c][2 * j],     a0);
            a1 = fma2(x0[2 * j + 1], p[c][2 * j + 1], a1);
            b0 = fma2(x1[2 * j],     p[c][2 * j],     b0);
            b1 = fma2(x1[2 * j + 1], p[c][2 * j + 1], b1);
          }
          float l0 = hadd2(add2(a0, a1));
          float l1 = hadd2(add2(b0, b1));
          float e0 = ex2f(l0);
          float e1 = ex2f(l1);
          Z0[c] += e0; Z1[c] += e1;
          ull e02 = pack2(e0), e12 = pack2(e1);
#pragma unroll
          for (int j = 0; j < 8; ++j) {
            ull t = fma2(e02, x0[j], y[c][j]);
            y[c][j] = fma2(e12, x1[j], t);
          }
        }
      }
      float Z[2] = {Z0[0] + Z1[0], Z0[1] + Z1[1]};

      // 3-level warp reduction -> 4 partials (lanes 0..3)
#pragma unroll
      for (int off = 16; off >= 4; off >>= 1) {
#pragma unroll
        for (int c = 0; c < 2; ++c) {
          Z[c] += __shfl_xor_sync(0xffffffffu, Z[c], off);
#pragma unroll
          for (int j = 0; j < 8; ++j)
            y[c][j] = add2(y[c][j], __shfl_xor_sync(0xffffffffu, y[c][j], off));
        }
      }
      if (lane < 4) {
#pragma unroll
        for (int c = 0; c < 2; ++c) {
          sm->partZ[chunk][lane][mlb + c] = Z[c];
#pragma unroll
          for (int j = 0; j < 8; ++j)
            *reinterpret_cast<ull*>(&sm->party[chunk][lane][mlb + c][2 * j]) = y[c][j];
        }
      }
    }
    __syncthreads();

    // ---- per-capsule epilogue: s = yW/Z, squash, Pacc += log2e * W v, new bound ----
    if (w < 8) {
      const int ml  = w * 2 + (lane >> 4);
      const int idx = lane & 15;
      float Z, yv;
      if (it == 0) {
        Z = 2048.f;
      } else {
        Z = 0.f;
#pragma unroll
        for (int cg = 0; cg < 4; ++cg) Z += sm->partZ[0][cg][ml] + sm->partZ[1][cg][ml];
      }
      float s = 0.f;
#pragma unroll
      for (int d = 0; d < 16; ++d) {
        if (it == 0) {
          yv = sm->sumx[d];
        } else {
          yv = 0.f;
#pragma unroll
          for (int cg = 0; cg < 4; ++cg)
            yv += sm->party[0][cg][ml][d] + sm->party[1][cg][ml][d];
        }
        s += yv * sm->Wdc[(ml * 16 + d) * 16 + idx];
      }
      s *= (1.f / Z);
      float nsq = s * s;
#pragma unroll
      for (int off = 1; off < 16; off <<= 1) nsq += __shfl_xor_sync(0xffffffffu, nsq, off);
      float norm = sqrtf(nsq);
      float fac  = nsq / ((1.f + nsq) * (norm + 1e-7f));
      float v    = s * fac;
      if (it == 2) {
        Y[(size_t)b * 512 + (m0 + ml) * 16 + idx] = v;
      } else {
        sm->vbuf[ml * 16 + idx] = v;
        __syncwarp();
        float pd = 0.f;
#pragma unroll
        for (int c = 0; c < 16; ++c)
          pd += sm->Wcd[(ml * 16 + c) * 16 + idx] * sm->vbuf[ml * 16 + c];
        float pn = sm->Pacc[ml * 16 + idx] + LOG2E * pd;
        sm->Pacc[ml * 16 + idx] = pn;
        float cn = pn * pn;
#pragma unroll
        for (int off = 1; off < 16; off <<= 1) cn += __shfl_xor_sync(0xffffffffu, cn, off);
        if (idx == 0) sm->bnd[ml] = sqrtf(cn) * sm->mxnorm;
      }
    }
    __syncthreads();
  }
}

extern "C" void kernel_launch(void* const* d_in, const int* in_sizes, int n_in,
                              void* d_out, int out_size) {
  (void)in_sizes; (void)n_in; (void)out_size;
  const float* X  = (const float*)d_in[0];   // inputs (64, 2048, 16)
  const float* Wg = (const float*)d_in[1];   // W (16, 32, 16)
  float* Y = (float*)d_out;                  // v (64, 32, 16)
  cudaFuncSetAttribute(caps_routing_kernel,
                       cudaFuncAttributeMaxDynamicSharedMemorySize, (int)sizeof(Smem));
  caps_routing_kernel<<<128, THREADS, sizeof(Smem)>>>(X, Wg, Y);
}